// round 1
// baseline (speedup 1.0000x reference)
#include <cuda_runtime.h>
#include <cstdint>

#define NB 128
#define P  4
#define N_ATOMS_MAX 50000

// Scratch (device globals: allocation-free per harness rules)
__device__ float g_h[N_ATOMS_MAX * NB];
__device__ float g_agg[N_ATOMS_MAX * NB];
__device__ float g_t[N_ATOMS_MAX * NB];

// ---------------- helpers ----------------

__device__ __forceinline__ float sspf(float x) {
    // softplus(x) - log(2), numerically stable
    float e = __expf(-fabsf(x));
    return fmaxf(x, 0.0f) + __logf(1.0f + e) - 0.69314718055994531f;
}

__device__ __forceinline__ unsigned long long pack2(float x, float y) {
    unsigned long long r;
    asm("mov.b64 %0, {%1, %2};" : "=l"(r) : "f"(x), "f"(y));
    return r;
}
__device__ __forceinline__ unsigned long long dupf(float w) {
    unsigned long long r;
    asm("mov.b64 %0, {%1, %1};" : "=l"(r) : "f"(w));
    return r;
}
__device__ __forceinline__ void unpack2(unsigned long long v, float& x, float& y) {
    asm("mov.b64 {%0, %1}, %2;" : "=f"(x), "=f"(y) : "l"(v));
}
__device__ __forceinline__ void fma2(unsigned long long& d,
                                     unsigned long long a,
                                     unsigned long long b) {
    // d = a*b + d  (packed 2x fp32)
    asm("fma.rn.f32x2 %0, %1, %2, %3;" : "=l"(d) : "l"(a), "l"(b), "l"(d));
}

// ---------------- zero ----------------

__global__ void zero_kernel(float* __restrict__ p, int n) {
    for (int i = blockIdx.x * blockDim.x + threadIdx.x; i < n;
         i += gridDim.x * blockDim.x)
        p[i] = 0.0f;
}

// ---------------- generic row GEMM:  Y = [ssp](X @ W + b)  (K = N = 128) ----
// One thread per output column j; W[:,j] register-resident; 4 rows / iter.

template <bool DOSSP>
__global__ __launch_bounds__(128, 2) void rowmm_kernel(
    const float* __restrict__ X, const float* __restrict__ W,
    const float* __restrict__ b, float* __restrict__ Y, int nrows) {
    const int j = threadIdx.x;

    float wr[NB];
#pragma unroll
    for (int k = 0; k < NB; k++) wr[k] = W[k * NB + j];
    const float bj = b[j];

    __shared__ __align__(16) float xsh[NB * P];  // layout [k][r]

    const int ngroups = (nrows + P - 1) / P;
    for (int g = blockIdx.x; g < ngroups; g += gridDim.x) {
        const int row0 = g * P;
        __syncthreads();
#pragma unroll
        for (int r = 0; r < P; r++) {
            int row = row0 + r;
            xsh[j * P + r] = (row < nrows) ? X[row * NB + j] : 0.0f;
        }
        __syncthreads();

        unsigned long long a01 = pack2(bj, bj);
        unsigned long long a23 = a01;
        const ulonglong2* xs2 = (const ulonglong2*)xsh;
#pragma unroll
        for (int k = 0; k < NB; k++) {
            ulonglong2 uv = xs2[k];
            unsigned long long wd = dupf(wr[k]);
            fma2(a01, uv.x, wd);
            fma2(a23, uv.y, wd);
        }
        float y0, y1, y2, y3;
        unpack2(a01, y0, y1);
        unpack2(a23, y2, y3);
        if (DOSSP) {
            y0 = sspf(y0); y1 = sspf(y1); y2 = sspf(y2); y3 = sspf(y3);
        }
        float yv[P] = {y0, y1, y2, y3};
#pragma unroll
        for (int r = 0; r < P; r++) {
            int row = row0 + r;
            if (row < nrows) Y[row * NB + j] = yv[r];
        }
    }
}

// ---------------- fused pair kernel ----------------
// Per pair e: u = ssp(f_ij[e] @ Wf1 + bf1); w = (u @ Wf2 + bf2) * rcut[e];
//             agg[idx_i[e]] += h[idx_j[e]] * w
// Thread j owns column j; Wf1[:,j] (20) and Wf2[:,j] (128) register-resident.

__global__ __launch_bounds__(128, 2) void pair_kernel(
    const float* __restrict__ f_ij, const float* __restrict__ rcut,
    const float* __restrict__ Wf1, const float* __restrict__ bf1,
    const float* __restrict__ Wf2, const float* __restrict__ bf2,
    const int* __restrict__ idx_i, const int* __restrict__ idx_j,
    const float* __restrict__ h, float* __restrict__ agg, int npairs) {
    const int j = threadIdx.x;

    float w1r[20];
#pragma unroll
    for (int k = 0; k < 20; k++) w1r[k] = Wf1[k * NB + j];
    const float b1 = bf1[j];

    float w2r[NB];
#pragma unroll
    for (int k = 0; k < NB; k++) w2r[k] = Wf2[k * NB + j];
    const float b2 = bf2[j];

    __shared__ __align__(16) float fsh[20 * P];   // [k][p]
    __shared__ __align__(16) float ush[NB * P];   // [k][p]
    __shared__ int   iish[P];
    __shared__ int   ijsh[P];
    __shared__ float rcsh[P];

    const int niter = (npairs + P - 1) / P;
    for (int it = blockIdx.x; it < niter; it += gridDim.x) {
        const int base = it * P;
        __syncthreads();
        if (j < 20 * P) {
            int p = j / 20, k = j % 20;
            int e = base + p;
            fsh[k * P + p] = (e < npairs) ? f_ij[e * 20 + k] : 0.0f;
        }
        if (j >= 96 && j < 96 + P) {
            int p = j - 96;
            int e = base + p;
            bool v = (e < npairs);
            iish[p] = v ? idx_i[e] : 0;
            ijsh[p] = v ? idx_j[e] : 0;
            rcsh[p] = v ? rcut[e] : 0.0f;
        }
        __syncthreads();

        // stage 1: u[p][j] = ssp(sum_k f[p][k] * Wf1[k][j] + b1)
        unsigned long long u01 = pack2(b1, b1);
        unsigned long long u23 = u01;
        const ulonglong2* fs2 = (const ulonglong2*)fsh;
#pragma unroll
        for (int k = 0; k < 20; k++) {
            ulonglong2 fv = fs2[k];
            unsigned long long wd = dupf(w1r[k]);
            fma2(u01, fv.x, wd);
            fma2(u23, fv.y, wd);
        }
        float u0, u1, u2, u3;
        unpack2(u01, u0, u1);
        unpack2(u23, u2, u3);
        float4 uo = make_float4(sspf(u0), sspf(u1), sspf(u2), sspf(u3));
        ((float4*)ush)[j] = uo;  // conflict-free STS.128; layout [k=j][p]
        __syncthreads();

        // stage 2: w[p][j] = sum_k u[p][k] * Wf2[k][j] + b2
        unsigned long long a01 = pack2(b2, b2);
        unsigned long long a23 = a01;
        const ulonglong2* us2 = (const ulonglong2*)ush;
#pragma unroll
        for (int k = 0; k < NB; k++) {
            ulonglong2 uv = us2[k];  // broadcast LDS.128
            unsigned long long wd = dupf(w2r[k]);
            fma2(a01, uv.x, wd);
            fma2(a23, uv.y, wd);
        }
        float a0, a1, a2, a3;
        unpack2(a01, a0, a1);
        unpack2(a23, a2, a3);
        float wv[P] = {a0 * rcsh[0], a1 * rcsh[1], a2 * rcsh[2], a3 * rcsh[3]};

#pragma unroll
        for (int p = 0; p < P; p++) {
            float hv = h[ijsh[p] * NB + j];               // L2-resident gather
            atomicAdd(&agg[iish[p] * NB + j], hv * wv[p]); // spread REDG
        }
    }
}

// ---------------- launch ----------------

extern "C" void kernel_launch(void* const* d_in, const int* in_sizes, int n_in,
                              void* d_out, int out_size) {
    const float* x    = (const float*)d_in[0];
    const float* f_ij = (const float*)d_in[1];
    const float* rcut = (const float*)d_in[2];
    const float* W_in = (const float*)d_in[3];
    const float* b_in = (const float*)d_in[4];
    const float* Wf1  = (const float*)d_in[5];
    const float* bf1  = (const float*)d_in[6];
    const float* Wf2  = (const float*)d_in[7];
    const float* bf2  = (const float*)d_in[8];
    const float* Wo1  = (const float*)d_in[9];
    const float* bo1  = (const float*)d_in[10];
    const float* Wo2  = (const float*)d_in[11];
    const float* bo2  = (const float*)d_in[12];
    const int* idx_i  = (const int*)d_in[13];
    const int* idx_j  = (const int*)d_in[14];

    const int natoms = in_sizes[0] / NB;
    const int npairs = in_sizes[2];
    float* out = (float*)d_out;

    float *hp, *aggp, *tp;
    cudaGetSymbolAddress((void**)&hp, g_h);
    cudaGetSymbolAddress((void**)&aggp, g_agg);
    cudaGetSymbolAddress((void**)&tp, g_t);

    const int grid = 148 * 8;

    zero_kernel<<<2048, 256>>>(aggp, natoms * NB);
    rowmm_kernel<false><<<grid, 128>>>(x, W_in, b_in, hp, natoms);
    pair_kernel<<<grid, 128>>>(f_ij, rcut, Wf1, bf1, Wf2, bf2, idx_i, idx_j,
                               hp, aggp, npairs);
    rowmm_kernel<true><<<grid, 128>>>(aggp, Wo1, bo1, tp, natoms);
    rowmm_kernel<false><<<grid, 128>>>(tp, Wo2, bo2, out, natoms);
}

// round 4
// speedup vs baseline: 1.0393x; 1.0393x over previous
#include <cuda_runtime.h>
#include <cstdint>

#define NB 128
#define P  8
#define N_ATOMS_MAX 50000

// Scratch (device globals: allocation-free per harness rules)
__device__ float g_h[N_ATOMS_MAX * NB];
__device__ float g_agg[N_ATOMS_MAX * NB];
__device__ float g_t[N_ATOMS_MAX * NB];

// ---------------- helpers ----------------

__device__ __forceinline__ float sspf(float x) {
    float e = __expf(-fabsf(x));
    return fmaxf(x, 0.0f) + __logf(1.0f + e) - 0.69314718055994531f;
}
__device__ __forceinline__ unsigned long long pack2(float x, float y) {
    unsigned long long r; asm("mov.b64 %0, {%1, %2};" : "=l"(r) : "f"(x), "f"(y)); return r;
}
__device__ __forceinline__ unsigned long long dupf(float w) {
    unsigned long long r; asm("mov.b64 %0, {%1, %1};" : "=l"(r) : "f"(w)); return r;
}
__device__ __forceinline__ void unpack2(unsigned long long v, float& x, float& y) {
    asm("mov.b64 {%0, %1}, %2;" : "=f"(x), "=f"(y) : "l"(v));
}
__device__ __forceinline__ void fma2(unsigned long long& d,
                                     unsigned long long a, unsigned long long b) {
    asm("fma.rn.f32x2 %0, %1, %2, %3;" : "=l"(d) : "l"(a), "l"(b), "l"(d));
}
__device__ __forceinline__ void red4(float* p, float a, float b, float c, float d) {
    asm volatile("red.global.add.v4.f32 [%0], {%1,%2,%3,%4};"
                 :: "l"(p), "f"(a), "f"(b), "f"(c), "f"(d) : "memory");
}

// ---------------- zero ----------------
__global__ void zero_kernel(float4* __restrict__ p, int n4) {
    int i = blockIdx.x * blockDim.x + threadIdx.x;
    if (i < n4) p[i] = make_float4(0.f, 0.f, 0.f, 0.f);
}

// ---------------- row GEMM: Y = [ssp](X @ W + b), K=N=128 ----------------
template <bool DOSSP>
__global__ __launch_bounds__(128, 2) void rowmm_kernel(
    const float* __restrict__ X, const float* __restrict__ W,
    const float* __restrict__ b, float* __restrict__ Y, int nrows) {
    const int j = threadIdx.x;
    float wr[NB];
#pragma unroll
    for (int k = 0; k < NB; k++) wr[k] = W[k * NB + j];
    const float bj = b[j];
    __shared__ __align__(16) float xsh[NB * 4];
    const int ngroups = (nrows + 3) / 4;
    for (int g = blockIdx.x; g < ngroups; g += gridDim.x) {
        const int row0 = g * 4;
        __syncthreads();
#pragma unroll
        for (int r = 0; r < 4; r++) {
            int row = row0 + r;
            xsh[j * 4 + r] = (row < nrows) ? X[row * NB + j] : 0.0f;
        }
        __syncthreads();
        unsigned long long a01 = pack2(bj, bj), a23 = a01;
        const ulonglong2* xs2 = (const ulonglong2*)xsh;
#pragma unroll
        for (int k = 0; k < NB; k++) {
            ulonglong2 uv = xs2[k];
            unsigned long long wd = dupf(wr[k]);
            fma2(a01, uv.x, wd);
            fma2(a23, uv.y, wd);
        }
        float y0, y1, y2, y3;
        unpack2(a01, y0, y1); unpack2(a23, y2, y3);
        if (DOSSP) { y0 = sspf(y0); y1 = sspf(y1); y2 = sspf(y2); y3 = sspf(y3); }
        float yv[4] = {y0, y1, y2, y3};
#pragma unroll
        for (int r = 0; r < 4; r++) {
            int row = row0 + r;
            if (row < nrows) Y[row * NB + j] = yv[r];
        }
    }
}

// ---------------- fused pair kernel (P = 8 pairs / block-iter) ----------------
// stage1: u[p][j] = ssp(f[p] @ Wf1[:,j] + bf1[j])     (thread j owns column j)
// stage2: w[p][j] = (u[p] @ Wf2[:,j] + bf2[j]) * rcut[p]
// epilogue (warp-per-pair): agg[idx_i[p]] += h[idx_j[p]] * w[p]  via red.v4

__global__ __launch_bounds__(128, 2) void pair_kernel(
    const float* __restrict__ f_ij, const float* __restrict__ rcut,
    const float* __restrict__ Wf1, const float* __restrict__ bf1,
    const float* __restrict__ Wf2, const float* __restrict__ bf2,
    const int* __restrict__ idx_i, const int* __restrict__ idx_j,
    const float* __restrict__ h, float* __restrict__ agg, int npairs) {
    const int j = threadIdx.x;
    const int wid = j >> 5;
    const int lane = j & 31;

    float w1r[20];
#pragma unroll
    for (int k = 0; k < 20; k++) w1r[k] = Wf1[k * NB + j];
    const float b1 = bf1[j];

    float w2r[NB];
#pragma unroll
    for (int k = 0; k < NB; k++) w2r[k] = Wf2[k * NB + j];
    const float b2 = bf2[j];

    __shared__ __align__(16) float fsh[20 * P];    // [k][p]
    __shared__ __align__(16) float ush[NB * P];    // [k][p]
    __shared__ __align__(16) float wsh[P * NB];    // [p][j]
    __shared__ int   iish[P];
    __shared__ int   ijsh[P];
    __shared__ float rcsh[P];

    const int niter = (npairs + P - 1) / P;
    for (int it = blockIdx.x; it < niter; it += gridDim.x) {
        const int base = it * P;
        __syncthreads();  // previous epilogue done before smem overwrite

        // --- tile loads: f (160 floats = 40 float4), idx, rcut ---
        if (j < 40) {
            int e4 = base * 20 + j * 4;  // float index into f_ij
            float4 fv;
            if (base + P <= npairs) {
                fv = ((const float4*)f_ij)[base * 5 + j];
            } else {
                float t[4];
#pragma unroll
                for (int c = 0; c < 4; c++) {
                    int g = e4 + c;
                    t[c] = (g < npairs * 20) ? f_ij[g] : 0.0f;
                }
                fv = make_float4(t[0], t[1], t[2], t[3]);
            }
            float tv[4] = {fv.x, fv.y, fv.z, fv.w};
#pragma unroll
            for (int c = 0; c < 4; c++) {
                int g = j * 4 + c;       // 0..159 within tile
                int p = g / 20, k = g - p * 20;
                fsh[k * P + p] = tv[c];
            }
        }
        if (j >= 64 && j < 64 + P) {
            int p = j - 64;
            int e = base + p;
            bool v = (e < npairs);
            iish[p] = v ? idx_i[e] : 0;
            ijsh[p] = v ? idx_j[e] : 0;
            rcsh[p] = v ? rcut[e] : 0.0f;
        }
        __syncthreads();

        // --- stage 1 ---
        unsigned long long u01 = pack2(b1, b1), u23 = u01, u45 = u01, u67 = u01;
        {
            const ulonglong2* fs2 = (const ulonglong2*)fsh;  // 16B units, 2 per k
#pragma unroll
            for (int k = 0; k < 20; k++) {
                ulonglong2 fa = fs2[2 * k];
                ulonglong2 fb = fs2[2 * k + 1];
                unsigned long long wd = dupf(w1r[k]);
                fma2(u01, fa.x, wd);
                fma2(u23, fa.y, wd);
                fma2(u45, fb.x, wd);
                fma2(u67, fb.y, wd);
            }
        }
        {
            float v[P];
            unpack2(u01, v[0], v[1]); unpack2(u23, v[2], v[3]);
            unpack2(u45, v[4], v[5]); unpack2(u67, v[6], v[7]);
#pragma unroll
            for (int p = 0; p < P; p++) v[p] = sspf(v[p]);
            float4* up = (float4*)(ush + j * P);
            up[0] = make_float4(v[0], v[1], v[2], v[3]);
            up[1] = make_float4(v[4], v[5], v[6], v[7]);
        }
        __syncthreads();

        // --- stage 2 ---
        unsigned long long a01 = pack2(b2, b2), a23 = a01, a45 = a01, a67 = a01;
        {
            const ulonglong2* us2 = (const ulonglong2*)ush;
#pragma unroll
            for (int k = 0; k < NB; k++) {
                ulonglong2 ua = us2[2 * k];      // broadcast LDS.128
                ulonglong2 ub = us2[2 * k + 1];
                unsigned long long wd = dupf(w2r[k]);
                fma2(a01, ua.x, wd);
                fma2(a23, ua.y, wd);
                fma2(a45, ub.x, wd);
                fma2(a67, ub.y, wd);
            }
        }
        {
            float v[P];
            unpack2(a01, v[0], v[1]); unpack2(a23, v[2], v[3]);
            unpack2(a45, v[4], v[5]); unpack2(a67, v[6], v[7]);
#pragma unroll
            for (int p = 0; p < P; p++) wsh[p * NB + j] = v[p] * rcsh[p];
        }
        __syncthreads();

        // --- epilogue: warp handles pairs 2*wid, 2*wid+1 ---
#pragma unroll
        for (int q = 0; q < 2; q++) {
            int p = wid * 2 + q;
            int ii = iish[p];
            int ij = ijsh[p];
            float4 wv = ((const float4*)(wsh + p * NB))[lane];
            float4 hv = ((const float4*)(h + (size_t)ij * NB))[lane];
            red4(agg + (size_t)ii * NB + lane * 4,
                 wv.x * hv.x, wv.y * hv.y, wv.z * hv.z, wv.w * hv.w);
        }
    }
}

// ---------------- launch ----------------
extern "C" void kernel_launch(void* const* d_in, const int* in_sizes, int n_in,
                              void* d_out, int out_size) {
    const float* x    = (const float*)d_in[0];
    const float* f_ij = (const float*)d_in[1];
    const float* rcut = (const float*)d_in[2];
    const float* W_in = (const float*)d_in[3];
    const float* b_in = (const float*)d_in[4];
    const float* Wf1  = (const float*)d_in[5];
    const float* bf1  = (const float*)d_in[6];
    const float* Wf2  = (const float*)d_in[7];
    const float* bf2  = (const float*)d_in[8];
    const float* Wo1  = (const float*)d_in[9];
    const float* bo1  = (const float*)d_in[10];
    const float* Wo2  = (const float*)d_in[11];
    const float* bo2  = (const float*)d_in[12];
    const int* idx_i  = (const int*)d_in[13];
    const int* idx_j  = (const int*)d_in[14];

    const int natoms = in_sizes[0] / NB;
    const int npairs = in_sizes[2];
    float* out = (float*)d_out;

    float *hp, *aggp, *tp;
    cudaGetSymbolAddress((void**)&hp, g_h);
    cudaGetSymbolAddress((void**)&aggp, g_agg);
    cudaGetSymbolAddress((void**)&tp, g_t);

    const int grid = 148 * 8;
    const int n4 = natoms * NB / 4;
    zero_kernel<<<(n4 + 255) / 256, 256>>>((float4*)aggp, n4);
    rowmm_kernel<false><<<grid, 128>>>(x, W_in, b_in, hp, natoms);
    pair_kernel<<<148 * 2, 128>>>(f_ij, rcut, Wf1, bf1, Wf2, bf2,
                                  idx_i, idx_j, hp, aggp, npairs);
    rowmm_kernel<true><<<grid, 128>>>(aggp, Wo1, bo1, tp, natoms);
    rowmm_kernel<false><<<grid, 128>>>(tp, Wo2, bo2, out, natoms);
}